// round 2
// baseline (speedup 1.0000x reference)
#include <cuda_runtime.h>

// ---------------------------------------------------------------------------
// MultiscaleDecomposedConv1D
//   B=8, S=8, T=4096, C_IN=128, C_OUT=256, KSIZE_T=9, KSIZE_S=3
//   Stage A: synthesize per-scale time kernels W[s][tap][i][o] from Fourier coeffs
//   Stage B: scale-axis 3-tap conv (edge-repeat pad) -> xs
//   Stage C: per-(b,s) time conv as implicit GEMM (M=4096, N=256, K=1152),
//            fp32 via packed fma.rn.f32x2 (FFMA2) for full-rate fp32.
// ---------------------------------------------------------------------------

#define PI_F 3.14159274101257324f

// Scratch (device globals: allocation-free per harness rules)
__device__ float g_W[8 * 9 * 128 * 256];            // 9.4 MB synthesized kernels
__device__ float g_xs[(size_t)8 * 8 * 4096 * 128];  // 128 MB scale-conv output

__constant__ float c_scales[8] = {-1.5f, -1.0f, -0.5f, 0.0f, 0.5f, 1.0f, 1.5f, 2.0f};

// ---------------------------------------------------------------------------
// packed f32x2 helpers
// ---------------------------------------------------------------------------
__device__ __forceinline__ unsigned long long ffma2(unsigned long long a,
                                                    unsigned long long b,
                                                    unsigned long long c) {
    unsigned long long d;
    asm("fma.rn.f32x2 %0, %1, %2, %3;" : "=l"(d) : "l"(a), "l"(b), "l"(c));
    return d;
}
__device__ __forceinline__ unsigned long long splat2(float a) {
    unsigned long long r;
    asm("mov.b64 %0, {%1, %1};" : "=l"(r) : "f"(a));
    return r;
}
__device__ __forceinline__ unsigned long long pack2(float lo, float hi) {
    unsigned long long r;
    asm("mov.b64 %0, {%1, %2};" : "=l"(r) : "f"(lo), "f"(hi));
    return r;
}
__device__ __forceinline__ void unpack2(unsigned long long v, float& lo, float& hi) {
    asm("mov.b64 {%0, %1}, %2;" : "=f"(lo), "=f"(hi) : "l"(v));
}

// ---------------------------------------------------------------------------
// Stage A: kernel synthesis
//   W[s][tap][i][o] = 2^alpha * mask(|u|<=1) * sum_c basis_c(u) * coeffs[c][i][o]
//   u = ((tap-4)/4) * 2^{-alpha}; basis = {1, sin(pi u), cos(pi u), sin(2pi u), cos(2pi u)}
//   grid: 72 blocks (s*9+tap), 256 threads (o), loop i
// ---------------------------------------------------------------------------
__global__ void wsynth_kernel(const float* __restrict__ coeffs) {
    int st  = blockIdx.x;         // s*9 + tap
    int s   = st / 9;
    int tap = st % 9;
    int o   = threadIdx.x;

    float alpha = c_scales[s];
    float u     = ((float)(tap - 4) * 0.25f) * exp2f(-alpha);
    float gain  = exp2f(alpha) * ((fabsf(u) <= 1.0f) ? 1.0f : 0.0f);

    float b1 = sinf(PI_F * u);
    float b2 = cosf(PI_F * u);
    float f2 = PI_F * 2.0f;
    float b3 = sinf(f2 * u);
    float b4 = cosf(f2 * u);

    const int KIO = 128 * 256;
    size_t base = (size_t)st * KIO + o;
    #pragma unroll 4
    for (int i = 0; i < 128; ++i) {
        const float* cp = coeffs + i * 256 + o;
        float acc = cp[0]            // basis_0 = cos(0) = 1
                  + b1 * cp[1 * KIO]
                  + b2 * cp[2 * KIO]
                  + b3 * cp[3 * KIO]
                  + b4 * cp[4 * KIO];
        g_W[base + (size_t)i * 256] = gain * acc;
    }
}

// ---------------------------------------------------------------------------
// Stage B: scale-axis conv (edge-repeat pad on S axis)
//   xs[b,s,t,c] = w0*x[b,max(s-1,0)] + w1*x[b,s] + w2*x[b,min(s+1,7)]
//   w_j from coeffs_scale with basis {1, sin(pi u), cos(pi u)}, u in {-1,0,1}
//   one float4 per thread; 8,388,608 float4 total
// ---------------------------------------------------------------------------
__global__ void sconv_kernel(const float* __restrict__ x,
                             const float* __restrict__ cs) {
    int idx = blockIdx.x * blockDim.x + threadIdx.x;  // float4 index

    float sn = sinf(PI_F);    // sin(pi) residual (matches fp32 reference)
    float cn = cosf(PI_F);    // ~ -1
    float c0 = cs[0], c1 = cs[1], c2 = cs[2];
    float w0 = c0 - c1 * sn + c2 * cn;   // u = -1: sin(-pi) = -sin(pi)
    float w1 = c0 + c2;                  // u =  0: sin=0, cos=1
    float w2 = c0 + c1 * sn + c2 * cn;   // u = +1

    int c4 = idx & 31;
    int t  = (idx >> 5) & 4095;
    int s  = (idx >> 17) & 7;
    int b  = idx >> 20;
    int sm = max(s - 1, 0);
    int sp = min(s + 1, 7);

    const size_t rowstride = 4096 * 32;  // float4 per (b,s) row
    size_t bbase = (size_t)b * 8 * rowstride + (size_t)t * 32 + c4;

    const float4* xp = reinterpret_cast<const float4*>(x);
    float4 a = xp[bbase + (size_t)sm * rowstride];
    float4 m = xp[bbase + (size_t)s  * rowstride];
    float4 p = xp[bbase + (size_t)sp * rowstride];

    float4 r;
    r.x = w0 * a.x + w1 * m.x + w2 * p.x;
    r.y = w0 * a.y + w1 * m.y + w2 * p.y;
    r.z = w0 * a.z + w1 * m.z + w2 * p.z;
    r.w = w0 * a.w + w1 * m.w + w2 * p.w;

    reinterpret_cast<float4*>(g_xs)[bbase + (size_t)s * rowstride] = r;
}

// ---------------------------------------------------------------------------
// Stage C: time conv as implicit GEMM
//   out[bs, t, o] = sum_{tap,i} xs[bs, t+tap-4, i] * W[s][tap][i][o]
//   block: 256 thr, tile M=64 (time) x N=128 (out-ch)
//   warp w -> rows [8w, 8w+8); lane -> 4 consecutive o (2 packed f32x2 accums)
//   A tile (72x128) resident in smem for whole K loop (broadcast reads)
//   B streamed in 8x128 chunks (conflict-free LDS.128)
// ---------------------------------------------------------------------------
__global__ void __launch_bounds__(256, 2)
tconv_kernel(float* __restrict__ out) {
    __shared__ float sA[72][128];
    __shared__ float sB[8][128];

    int tid  = threadIdx.x;
    int bs   = blockIdx.z;           // b*8 + s
    int sIdx = bs & 7;
    int t0   = blockIdx.x * 64;
    int ob   = blockIdx.y * 128;

    // ---- load A tile (time rows t0-4 .. t0+67, zero-padded) ----
    const float* xsp = g_xs + (size_t)bs * (4096 * 128);
    for (int l = tid; l < 72 * 32; l += 256) {
        int row = l >> 5;
        int c4  = l & 31;
        int t   = t0 - 4 + row;
        float4 v = make_float4(0.f, 0.f, 0.f, 0.f);
        if (t >= 0 && t < 4096)
            v = *reinterpret_cast<const float4*>(xsp + (size_t)t * 128 + c4 * 4);
        *reinterpret_cast<float4*>(&sA[row][c4 * 4]) = v;
    }

    int warp  = tid >> 5;
    int lane  = tid & 31;
    int mbase = warp * 8;
    int nb    = lane * 4;

    unsigned long long acc[8][2];
    #pragma unroll
    for (int m = 0; m < 8; ++m) { acc[m][0] = 0ull; acc[m][1] = 0ull; }

    const float* Wbase = g_W + (size_t)(sIdx * 9) * (128 * 256) + ob;

    for (int tap = 0; tap < 9; ++tap) {
        #pragma unroll 1
        for (int ic = 0; ic < 128; ic += 8) {
            __syncthreads();  // protect sB readers from previous chunk (and sA fill, 1st iter)
            // load B chunk: rows k = tap*128+ic .. +7, cols [ob, ob+128)
            float4 wv = *reinterpret_cast<const float4*>(
                Wbase + (size_t)(tap * 128 + ic + warp) * 256 + nb);
            *reinterpret_cast<float4*>(&sB[warp][nb]) = wv;
            __syncthreads();

            const float* ap = &sA[mbase + tap][ic];
            #pragma unroll
            for (int kk4 = 0; kk4 < 8; kk4 += 4) {
                // B pairs for 4 k-steps (LDS.128, conflict-free; pair via reg pack)
                unsigned long long bq0[4], bq1[4];
                #pragma unroll
                for (int j = 0; j < 4; ++j) {
                    float4 bv = *reinterpret_cast<const float4*>(&sB[kk4 + j][nb]);
                    bq0[j] = pack2(bv.x, bv.y);
                    bq1[j] = pack2(bv.z, bv.w);
                }
                #pragma unroll
                for (int m = 0; m < 8; ++m) {
                    float4 av = *reinterpret_cast<const float4*>(ap + m * 128 + kk4);
                    unsigned long long a0 = splat2(av.x);
                    unsigned long long a1 = splat2(av.y);
                    unsigned long long a2 = splat2(av.z);
                    unsigned long long a3 = splat2(av.w);
                    acc[m][0] = ffma2(a0, bq0[0], acc[m][0]);
                    acc[m][1] = ffma2(a0, bq1[0], acc[m][1]);
                    acc[m][0] = ffma2(a1, bq0[1], acc[m][0]);
                    acc[m][1] = ffma2(a1, bq1[1], acc[m][1]);
                    acc[m][0] = ffma2(a2, bq0[2], acc[m][0]);
                    acc[m][1] = ffma2(a2, bq1[2], acc[m][1]);
                    acc[m][0] = ffma2(a3, bq0[3], acc[m][0]);
                    acc[m][1] = ffma2(a3, bq1[3], acc[m][1]);
                }
            }
        }
    }

    // ---- epilogue: float4 stores, fully coalesced ----
    float* op = out + ((size_t)bs * 4096 + t0 + mbase) * 256 + ob + nb;
    #pragma unroll
    for (int m = 0; m < 8; ++m) {
        float4 r;
        unpack2(acc[m][0], r.x, r.y);
        unpack2(acc[m][1], r.z, r.w);
        *reinterpret_cast<float4*>(op + (size_t)m * 256) = r;
    }
}

// ---------------------------------------------------------------------------
// launch
//   d_in[0]: x_in          (8,8,4096,128) f32
//   d_in[1]: coeffs        (5,128,256)    f32
//   d_in[2]: coeffs_scale  (3,1,1)        f32
//   d_out  : (8,8,4096,256) f32
// ---------------------------------------------------------------------------
extern "C" void kernel_launch(void* const* d_in, const int* in_sizes, int n_in,
                              void* d_out, int out_size) {
    const float* x      = (const float*)d_in[0];
    const float* coeffs = (const float*)d_in[1];
    const float* cs     = (const float*)d_in[2];
    float* out          = (float*)d_out;

    wsynth_kernel<<<72, 256>>>(coeffs);
    sconv_kernel<<<32768, 256>>>(x, cs);
    tconv_kernel<<<dim3(64, 2, 64), 256>>>(out);
}